// round 16
// baseline (speedup 1.0000x reference)
#include <cuda_runtime.h>
#include <cstdint>

// ---------------- scratch (no allocations allowed) ----------------
__device__ float g_WqEffT[512 * 512];   // [n=h*64+e][k]
__device__ float g_WkEffT[512 * 512];
__device__ float g_WkT[512 * 512];
__device__ float g_WoT[512 * 512];
__device__ float g_biasQ[512];
__device__ float g_biasK[512];
__device__ float g_qhE[16 * 64 * 512];   // [z][e][t]
__device__ float g_khbE[16 * 64 * 512];  // [z][e][s]
__device__ float g_KpR[16 * 512 * 64];   // [z][s][d]
__device__ float g_part[64 * 512 * 64];  // [(z*4+sq)][t][d] unnormalized AV partial
__device__ float g_lpart[64 * 512];      // [(z*4+sq)][t] partial exp-sums

__device__ __forceinline__ uint32_t f2tf32(float x) {
    uint32_t u;
    asm("cvt.rna.tf32.f32 %0, %1;" : "=r"(u) : "f"(x));
    return u;
}
__device__ __forceinline__ float tanh_fast(float x) {
    float y;
    asm("tanh.approx.f32 %0, %1;" : "=f"(y) : "f"(x));
    return y;
}
__device__ __forceinline__ void mma_m16n8k8(float* d, const uint32_t* a,
                                            const uint32_t* b) {
    asm volatile(
        "mma.sync.aligned.m16n8k8.row.col.f32.tf32.tf32.f32 "
        "{%0,%1,%2,%3}, {%4,%5,%6,%7}, {%8,%9}, {%0,%1,%2,%3};"
        : "+f"(d[0]), "+f"(d[1]), "+f"(d[2]), "+f"(d[3])
        : "r"(a[0]), "r"(a[1]), "r"(a[2]), "r"(a[3]), "r"(b[0]), "r"(b[1]));
}

// ==================== merged prep kernel ====================
__global__ void __launch_bounds__(256) prep_all(
    const float* __restrict__ bq, const float* __restrict__ Wq_h,
    const float* __restrict__ bk, const float* __restrict__ Wk_h,
    const float* __restrict__ b_h, const float* __restrict__ Wq,
    const float* __restrict__ Wk, const float* __restrict__ Wo) {
    __shared__ float sm[2][64][68];
    const int bx = blockIdx.x, tid = threadIdx.x;
    if (bx < 4) {
        int i = bx * 256 + tid;
        int side = i >> 9, col = i & 511, h = col >> 6, e = col & 63;
        const float* bb = side ? bk : bq;
        const float* Wh = (side ? Wk_h : Wq_h) + h * 4096;
        float s = 0.f;
#pragma unroll 8
        for (int d = 0; d < 64; d++) s += bb[h * 64 + d] * Wh[d * 64 + e];
        if (side) g_biasK[col] = s + b_h[col];
        else      g_biasQ[col] = s;
    } else if (bx < 132) {
        int q = bx - 4;
        int side = q >> 6;
        q &= 63;
        int h = q >> 3, k0 = (q & 7) * 64;
        const float* W = side ? Wk : Wq;
        const float* Wh = (side ? Wk_h : Wq_h) + h * 4096;
        float* C = (side ? g_WkEffT : g_WqEffT) + h * 64 * 512;
#pragma unroll
        for (int r = 0; r < 4; r++) {
            int idx = tid + r * 256;
            int row = idx >> 4, c4 = (idx & 15) << 2;
            *(float4*)&sm[0][row][c4] = *(const float4*)&W[(long)(k0 + row) * 512 + h * 64 + c4];
            *(float4*)&sm[1][row][c4] = *(const float4*)&Wh[row * 64 + c4];
        }
        __syncthreads();
        const int tmm = (tid >> 4) * 4, tnn = (tid & 15) * 4;
        float acc[4][4] = {};
#pragma unroll 8
        for (int d = 0; d < 64; d++) {
            float a[4], b[4];
#pragma unroll
            for (int i = 0; i < 4; i++) a[i] = sm[0][tmm + i][d];
            *(float4*)b = *(const float4*)&sm[1][d][tnn];
#pragma unroll
            for (int i = 0; i < 4; i++)
#pragma unroll
                for (int j = 0; j < 4; j++) acc[i][j] += a[i] * b[j];
        }
#pragma unroll
        for (int i = 0; i < 4; i++)
#pragma unroll
            for (int j = 0; j < 4; j++)
                C[(long)(tnn + j) * 512 + k0 + tmm + i] = acc[i][j];
    } else {
        int q = bx - 132;
        int zz = q >> 8;
        q &= 255;
        int by = q >> 4, bxx = q & 15;
        const float* S = zz ? Wo : Wk;
        float* D = zz ? g_WoT : g_WkT;
        float (*t)[33] = (float(*)[33]) & sm[0][0][0];
        int lx = tid & 31, ly = tid >> 5;
        int x = bxx * 32 + lx, y0 = by * 32;
#pragma unroll
        for (int r = ly; r < 32; r += 8) t[r][lx] = S[(long)(y0 + r) * 512 + x];
        __syncthreads();
        int xo = y0 + lx;
#pragma unroll
        for (int r = ly; r < 32; r += 8) D[(long)(bxx * 32 + r) * 512 + xo] = t[lx][r];
    }
}

// ==================== tf32 mma.sync GEMM core (R14 proven form) ====================
// Double-buffered smem, K-chunk 32, dynamic chunk loop, 1-deep register stage.
// Tile MT x 64 (MT in {32,64}), 8 warps 2x4.
// C = A[Mx512] @ B^T (B K-major [512n][512k]) + bias.
// mode 0: row-major C. mode 1: [z][n&63][t] scatter. mode 2: [z][t][n&63].
template <int MT>
__device__ __forceinline__ void gemm_core(
    uint32_t* As, uint32_t* Bs,  // As: 2*ASTRIDE, Bs: 2*2048
    const float* __restrict__ A, const float* __restrict__ B,
    const float* __restrict__ bias, float* __restrict__ C,
    int m0, int n0, int mode) {
    constexpr int MI = MT / 32;          // mma m-tiles per warp
    constexpr int AR = MT / 32;          // A float4s per thread per chunk
    constexpr int ASTRIDE = (MT / 16) * 4 * 128;
    const int tid = threadIdx.x;
    const int wid = tid >> 5, lane = tid & 31;
    const int wm = wid >> 2, wn = wid & 3;

    float4 apf[AR], bpf[2];
    auto ldg = [&](int ch) {
        int k0 = ch << 5;
#pragma unroll
        for (int r = 0; r < AR; r++) {
            int j = tid + 256 * r;
            int row = j >> 3, c4 = (j & 7) << 2;
            apf[r] = *(const float4*)&A[(long)(m0 + row) * 512 + k0 + c4];
        }
#pragma unroll
        for (int r = 0; r < 2; r++) {
            int j = tid + 256 * r;
            int row = j >> 3, c4 = (j & 7) << 2;
            bpf[r] = *(const float4*)&B[(long)(n0 + row) * 512 + k0 + c4];
        }
    };
    auto sts = [&](int buf) {
#pragma unroll
        for (int r = 0; r < AR; r++) {
            int j = tid + 256 * r;
            int row = j >> 3, c4 = (j & 7) << 2;
            int ks = c4 >> 3, chi = (c4 >> 2) & 1;
            int mt = row >> 4, rlo = row & 15;
            int reg = (rlo >> 3) + (chi << 1);
            int off = buf * ASTRIDE + (mt * 4 + ks) * 128 + (rlo & 7) * 16 + reg;
            As[off + 0] = f2tf32(apf[r].x);
            As[off + 4] = f2tf32(apf[r].y);
            As[off + 8] = f2tf32(apf[r].z);
            As[off + 12] = f2tf32(apf[r].w);
        }
#pragma unroll
        for (int r = 0; r < 2; r++) {
            int j = tid + 256 * r;
            int row = j >> 3, c4 = (j & 7) << 2;
            int ks = c4 >> 3, chi = (c4 >> 2) & 1;
            int nt = row >> 3, g = row & 7;
            int off = buf * 2048 + (nt * 4 + ks) * 64 + g * 8 + chi;
            Bs[off + 0] = f2tf32(bpf[r].x);
            Bs[off + 2] = f2tf32(bpf[r].y);
            Bs[off + 4] = f2tf32(bpf[r].z);
            Bs[off + 6] = f2tf32(bpf[r].w);
        }
    };

    float acc[MI][2][4] = {};
    auto compute = [&](int buf) {
#pragma unroll
        for (int ks = 0; ks < 4; ks++) {
            uint32_t a[MI][4], b[2][2];
#pragma unroll
            for (int i = 0; i < MI; i++) {
                int mt = wm * MI + i;
                uint4 v = *(const uint4*)&As[buf * ASTRIDE + (mt * 4 + ks) * 128 + lane * 4];
                a[i][0] = v.x; a[i][1] = v.y; a[i][2] = v.z; a[i][3] = v.w;
            }
#pragma unroll
            for (int j = 0; j < 2; j++) {
                int nt = wn * 2 + j;
                uint2 v = *(const uint2*)&Bs[buf * 2048 + (nt * 4 + ks) * 64 + lane * 2];
                b[j][0] = v.x; b[j][1] = v.y;
            }
#pragma unroll
            for (int i = 0; i < MI; i++)
#pragma unroll
                for (int j = 0; j < 2; j++) mma_m16n8k8(acc[i][j], a[i], b[j]);
        }
    };

    ldg(0);
    sts(0);
    __syncthreads();
    for (int ch = 0; ch < 16; ch++) {
        if (ch + 1 < 16) ldg(ch + 1);
        compute(ch & 1);
        if (ch + 1 < 16) sts((ch + 1) & 1);
        __syncthreads();
    }

    const int g = lane >> 2, t4 = lane & 3;
#pragma unroll
    for (int i = 0; i < MI; i++)
#pragma unroll
        for (int j = 0; j < 2; j++) {
            int m = m0 + wm * (MI * 16) + i * 16 + g;
            int n = n0 + wn * 16 + j * 8 + t4 * 2;
            float c0 = acc[i][j][0], c1 = acc[i][j][1];
            float c2 = acc[i][j][2], c3 = acc[i][j][3];
            if (bias) {
                float b0 = bias[n], b1 = bias[n + 1];
                c0 += b0; c1 += b1; c2 += b0; c3 += b1;
            }
            if (mode == 0) {
                *(float2*)&C[(long)m * 512 + n] = make_float2(c0, c1);
                *(float2*)&C[(long)(m + 8) * 512 + n] = make_float2(c2, c3);
            } else if (mode == 1) {
                int bb = m >> 9, t = m & 511;
                long base0 = ((long)((bb << 3) + (n >> 6)) * 64 + (n & 63)) * 512;
                C[base0 + t] = c0;
                C[base0 + 512 + t] = c1;
                C[base0 + t + 8] = c2;
                C[base0 + 512 + t + 8] = c3;
            } else {
                int bb = m >> 9, t = m & 511;
                long r0 = ((long)((bb << 3) + (n >> 6)) * 512 + t) * 64 + (n & 63);
                *(float2*)&C[r0] = make_float2(c0, c1);
                *(float2*)&C[r0 + 8 * 64] = make_float2(c2, c3);
            }
        }
}

// three projections in one launch (z = task), 64x64 tiles (grid 384)
__global__ void __launch_bounds__(256) proj_mma(
    const float* __restrict__ query, const float* __restrict__ key,
    const float* __restrict__ bk) {
    __shared__ uint32_t As[2][2048], Bs[2][2048];  // 32 KB
    int task = blockIdx.z;
    int m0 = blockIdx.y * 64, n0 = blockIdx.x * 64;
    if (task == 0)
        gemm_core<64>(&As[0][0], &Bs[0][0], query, g_WqEffT, g_biasQ, g_qhE, m0, n0, 1);
    else if (task == 1)
        gemm_core<64>(&As[0][0], &Bs[0][0], key, g_WkEffT, g_biasK, g_khbE, m0, n0, 1);
    else
        gemm_core<64>(&As[0][0], &Bs[0][0], key, g_WkT, bk, g_KpR, m0, n0, 2);
}

// ==================== output projection with inlined partial-combine ====================
// out = (sum_q g_part[q] / sum_q g_lpart[q]) @ WoT^T + bo.
// 32x64 tile, grid (8, 32). A-load reads the 4 s-quarter partials directly and
// normalizes by inv_l (per merged-row, per head block; h = ch>>1 is chunk-constant).
__global__ void __launch_bounds__(256) outg_mma(
    const float* __restrict__ bo, float* __restrict__ out) {
    __shared__ uint32_t As[2][1024], Bs[2][2048];  // 24 KB
    constexpr int ASTRIDE = 1024;
    const int tid = threadIdx.x;
    const int wid = tid >> 5, lane = tid & 31;
    const int wm = wid >> 2, wn = wid & 3;
    const int m0 = blockIdx.y * 32, n0 = blockIdx.x * 64;
    const int arow = tid >> 3, ac4 = (tid & 7) << 2;
    const int brow2 = (tid + 256) >> 3;

    // this thread's merged row (fixed for all chunks)
    const int tg = m0 + arow;
    const int b = tg >> 9, t = tg & 511;

    // precompute 1/l for all 8 head blocks of this row
    float invl[8];
#pragma unroll
    for (int h = 0; h < 8; h++) {
        int zb = ((b << 3) + h) << 2;
        float l = g_lpart[(zb + 0) * 512 + t] + g_lpart[(zb + 1) * 512 + t] +
                  g_lpart[(zb + 2) * 512 + t] + g_lpart[(zb + 3) * 512 + t];
        invl[h] = __fdividef(1.f, l);
    }

    float4 apf, bpf[2];
    auto ldg = [&](int ch) {
        int h = ch >> 1;
        int doff = ((ch & 1) << 5) + ac4;
        long base = ((long)(((b << 3) + h) << 2)) * 32768 + (long)t * 64 + doff;
        float4 p0 = *(const float4*)&g_part[base];
        float4 p1 = *(const float4*)&g_part[base + 32768];
        float4 p2 = *(const float4*)&g_part[base + 65536];
        float4 p3 = *(const float4*)&g_part[base + 98304];
        float iv = invl[h];
        apf.x = ((p0.x + p1.x) + (p2.x + p3.x)) * iv;
        apf.y = ((p0.y + p1.y) + (p2.y + p3.y)) * iv;
        apf.z = ((p0.z + p1.z) + (p2.z + p3.z)) * iv;
        apf.w = ((p0.w + p1.w) + (p2.w + p3.w)) * iv;
        int k0 = ch << 5;
        bpf[0] = *(const float4*)&g_WoT[(long)(n0 + arow) * 512 + k0 + ac4];
        bpf[1] = *(const float4*)&g_WoT[(long)(n0 + brow2) * 512 + k0 + ac4];
    };
    auto sts = [&](int buf) {
        {
            int ks = ac4 >> 3, chi = (ac4 >> 2) & 1;
            int mt = arow >> 4, rlo = arow & 15;
            int reg = (rlo >> 3) + (chi << 1);
            int off = buf * ASTRIDE + (mt * 4 + ks) * 128 + (rlo & 7) * 16 + reg;
            As[0][off + 0] = f2tf32(apf.x);
            As[0][off + 4] = f2tf32(apf.y);
            As[0][off + 8] = f2tf32(apf.z);
            As[0][off + 12] = f2tf32(apf.w);
        }
#pragma unroll
        for (int r = 0; r < 2; r++) {
            int row = r ? brow2 : arow;
            int ks = ac4 >> 3, chi = (ac4 >> 2) & 1;
            int nt = row >> 3, g = row & 7;
            int off = buf * 2048 + (nt * 4 + ks) * 64 + g * 8 + chi;
            Bs[0][off + 0] = f2tf32(bpf[r].x);
            Bs[0][off + 2] = f2tf32(bpf[r].y);
            Bs[0][off + 4] = f2tf32(bpf[r].z);
            Bs[0][off + 6] = f2tf32(bpf[r].w);
        }
    };

    float acc[2][4] = {};
    auto compute = [&](int buf) {
#pragma unroll
        for (int ks = 0; ks < 4; ks++) {
            uint32_t a[4], bb[2][2];
            {
                uint4 v = *(const uint4*)&As[0][buf * ASTRIDE + (wm * 4 + ks) * 128 + lane * 4];
                a[0] = v.x; a[1] = v.y; a[2] = v.z; a[3] = v.w;
            }
#pragma unroll
            for (int j = 0; j < 2; j++) {
                int nt = wn * 2 + j;
                uint2 v = *(const uint2*)&Bs[0][buf * 2048 + (nt * 4 + ks) * 64 + lane * 2];
                bb[j][0] = v.x; bb[j][1] = v.y;
            }
#pragma unroll
            for (int j = 0; j < 2; j++) mma_m16n8k8(acc[j], a, bb[j]);
        }
    };

    ldg(0);
    sts(0);
    __syncthreads();
    for (int ch = 0; ch < 16; ch++) {
        if (ch + 1 < 16) ldg(ch + 1);
        compute(ch & 1);
        if (ch + 1 < 16) sts((ch + 1) & 1);
        __syncthreads();
    }

    const int g = lane >> 2, t4 = lane & 3;
#pragma unroll
    for (int j = 0; j < 2; j++) {
        int m = m0 + wm * 16 + g;
        int n = n0 + wn * 16 + j * 8 + t4 * 2;
        float b0 = bo[n], b1 = bo[n + 1];
        *(float2*)&out[(long)m * 512 + n] = make_float2(acc[j][0] + b0, acc[j][1] + b1);
        *(float2*)&out[(long)(m + 8) * 512 + n] = make_float2(acc[j][2] + b0, acc[j][3] + b1);
    }
}

// ==================== fused score + exp + AV, s-split partials ====================
// grid (16 t-tiles, 16 z, 4 s-quarters). Per CTA: rows t0..t0+31 of one (b,h),
// s-chunks [2*sq, 2*sq+2). Scores are bounded (|score| ~< 1.5), so exp is taken
// WITHOUT max-subtraction; partials combine by plain summation in outg_mma.
__global__ void __launch_bounds__(256) fused_attn(const float* __restrict__ va) {
    const int t0 = blockIdx.x * 32;
    const int z = blockIdx.y;
    const int sq = blockIdx.z;
    const int h = z & 7;
    __shared__ float qse[64][36];   // [e][t]
    __shared__ float kse[64][68];   // [e][s]; rows 0..31 reused as p[t][s]
    __shared__ float kp[64][68];    // [s][d]
    __shared__ float vsh[64];
    const int tid = threadIdx.x;
    const float* qbase = g_qhE + (long)z * 32768;
    const float* kbase = g_khbE + (long)z * 32768;
    const float* kpbase = g_KpR + (long)z * 32768;

#pragma unroll
    for (int r = 0; r < 2; r++) {
        int idx = tid + r * 256;
        int row = idx >> 3, c4 = (idx & 7) << 2;
        *(float4*)&qse[row][c4] = *(const float4*)&qbase[(long)row * 512 + t0 + c4];
    }
    if (tid < 64) vsh[tid] = va[h * 64 + tid];

    const int tm = (tid >> 4) * 2, tn = (tid & 15) * 4;
    float out[2][4] = {};
    float lrow[2] = {0.f, 0.f};
    float* pbuf = &kse[0][0];

    for (int c = sq * 2; c < sq * 2 + 2; c++) {
        const int s0 = c * 64;
        __syncthreads();  // prior chunk consumers done with kse/kp
#pragma unroll
        for (int r = 0; r < 4; r++) {
            int idx = tid + r * 256;
            int row = idx >> 4, c4 = (idx & 15) << 2;
            *(float4*)&kse[row][c4] = *(const float4*)&kbase[(long)row * 512 + s0 + c4];
            *(float4*)&kp[row][c4] = *(const float4*)&kpbase[(long)(s0 + row) * 64 + c4];
        }
        __syncthreads();

        float sc[2][4] = {};
#pragma unroll 8
        for (int e = 0; e < 64; e++) {
            float vv = vsh[e];
            float2 q2 = *(const float2*)&qse[e][tm];
            float4 kv = *(const float4*)&kse[e][tn];
            sc[0][0] += vv * tanh_fast(q2.x + kv.x);
            sc[0][1] += vv * tanh_fast(q2.x + kv.y);
            sc[0][2] += vv * tanh_fast(q2.x + kv.z);
            sc[0][3] += vv * tanh_fast(q2.x + kv.w);
            sc[1][0] += vv * tanh_fast(q2.y + kv.x);
            sc[1][1] += vv * tanh_fast(q2.y + kv.y);
            sc[1][2] += vv * tanh_fast(q2.y + kv.z);
            sc[1][3] += vv * tanh_fast(q2.y + kv.w);
        }

        // p = exp(score) directly (bounded scores; no max subtraction needed)
#pragma unroll
        for (int i = 0; i < 2; i++) {
#pragma unroll
            for (int j = 0; j < 4; j++) sc[i][j] = __expf(sc[i][j]);
            lrow[i] += (sc[i][0] + sc[i][1]) + (sc[i][2] + sc[i][3]);
        }

        __syncthreads();  // all kse reads finished (pbuf aliases kse)
        *(float4*)&pbuf[tm * 68 + tn] = make_float4(sc[0][0], sc[0][1], sc[0][2], sc[0][3]);
        *(float4*)&pbuf[(tm + 1) * 68 + tn] = make_float4(sc[1][0], sc[1][1], sc[1][2], sc[1][3]);
        __syncthreads();

#pragma unroll 4
        for (int s = 0; s < 64; s++) {
            float p0 = pbuf[tm * 68 + s];
            float p1 = pbuf[(tm + 1) * 68 + s];
            float4 kv = *(const float4*)&kp[s][tn];
            out[0][0] += p0 * kv.x; out[0][1] += p0 * kv.y;
            out[0][2] += p0 * kv.z; out[0][3] += p0 * kv.w;
            out[1][0] += p1 * kv.x; out[1][1] += p1 * kv.y;
            out[1][2] += p1 * kv.z; out[1][3] += p1 * kv.w;
        }
    }

    // reduce lrow across the 16 threads sharing each row pair, write partials
#pragma unroll
    for (int o = 8; o; o >>= 1) {
        lrow[0] += __shfl_xor_sync(0xffffffffu, lrow[0], o);
        lrow[1] += __shfl_xor_sync(0xffffffffu, lrow[1], o);
    }
    long pb0 = ((long)((z << 2) + sq) * 512 + t0 + tm) * 64 + tn;
    *(float4*)&g_part[pb0] = make_float4(out[0][0], out[0][1], out[0][2], out[0][3]);
    *(float4*)&g_part[pb0 + 64] = make_float4(out[1][0], out[1][1], out[1][2], out[1][3]);
    if ((tid & 15) == 0) {
        int lb = ((z << 2) + sq) * 512 + t0 + tm;
        g_lpart[lb] = lrow[0];
        g_lpart[lb + 1] = lrow[1];
    }
}

// ---------------- launcher ----------------
extern "C" void kernel_launch(void* const* d_in, const int* in_sizes, int n_in,
                              void* d_out, int out_size) {
    const float* query = (const float*)d_in[0];
    const float* key   = (const float*)d_in[1];
    const float* Wq   = (const float*)d_in[3];
    const float* bq   = (const float*)d_in[4];
    const float* Wk   = (const float*)d_in[5];
    const float* bk   = (const float*)d_in[6];
    const float* Wq_h = (const float*)d_in[9];
    const float* Wk_h = (const float*)d_in[10];
    const float* va_h = (const float*)d_in[11];
    const float* b_h  = (const float*)d_in[12];
    const float* Wo   = (const float*)d_in[13];
    const float* bo   = (const float*)d_in[14];
    float* out = (float*)d_out;

    prep_all<<<644, 256>>>(bq, Wq_h, bk, Wk_h, b_h, Wq, Wk, Wo);
    proj_mma<<<dim3(8, 16, 3), 256>>>(query, key, bk);
    fused_attn<<<dim3(16, 16, 4), 256>>>(va_h);
    outg_mma<<<dim3(8, 32), 256>>>(bo, out);
}

// round 17
// speedup vs baseline: 1.1351x; 1.1351x over previous
#include <cuda_runtime.h>
#include <cstdint>

// ---------------- scratch (no allocations allowed) ----------------
__device__ float g_WqEffT[512 * 512];   // [n=h*64+e][k]
__device__ float g_WkEffT[512 * 512];
__device__ float g_WkT[512 * 512];
__device__ float g_WoT[512 * 512];
__device__ float g_biasQ[512];
__device__ float g_biasK[512];
__device__ float g_qhE[16 * 64 * 512];   // [z][e][t]
__device__ float g_khbE[16 * 64 * 512];  // [z][e][s]
__device__ float g_KpR[16 * 512 * 64];   // [z][s][d]
__device__ float g_part[64 * 512 * 64];  // [(z*4+sq)][t][d] unnormalized AV partial
__device__ float g_lpart[64 * 512];      // [(z*4+sq)][t] partial exp-sums
__device__ float g_merged[1024 * 512];   // [b*512+t][h*64+d]
__device__ int   g_cnt[256];             // [z*16 + t-tile] arrival counters

__device__ __forceinline__ uint32_t f2tf32(float x) {
    uint32_t u;
    asm("cvt.rna.tf32.f32 %0, %1;" : "=r"(u) : "f"(x));
    return u;
}
__device__ __forceinline__ float tanh_fast(float x) {
    float y;
    asm("tanh.approx.f32 %0, %1;" : "=f"(y) : "f"(x));
    return y;
}
__device__ __forceinline__ void mma_m16n8k8(float* d, const uint32_t* a,
                                            const uint32_t* b) {
    asm volatile(
        "mma.sync.aligned.m16n8k8.row.col.f32.tf32.tf32.f32 "
        "{%0,%1,%2,%3}, {%4,%5,%6,%7}, {%8,%9}, {%0,%1,%2,%3};"
        : "+f"(d[0]), "+f"(d[1]), "+f"(d[2]), "+f"(d[3])
        : "r"(a[0]), "r"(a[1]), "r"(a[2]), "r"(a[3]), "r"(b[0]), "r"(b[1]));
}

// ==================== merged prep kernel ====================
__global__ void __launch_bounds__(256) prep_all(
    const float* __restrict__ bq, const float* __restrict__ Wq_h,
    const float* __restrict__ bk, const float* __restrict__ Wk_h,
    const float* __restrict__ b_h, const float* __restrict__ Wq,
    const float* __restrict__ Wk, const float* __restrict__ Wo) {
    __shared__ float sm[2][64][68];
    const int bx = blockIdx.x, tid = threadIdx.x;
    if (bx < 4) {
        if (bx == 0) g_cnt[tid] = 0;  // reset combine counters every replay
        int i = bx * 256 + tid;
        int side = i >> 9, col = i & 511, h = col >> 6, e = col & 63;
        const float* bb = side ? bk : bq;
        const float* Wh = (side ? Wk_h : Wq_h) + h * 4096;
        float s = 0.f;
#pragma unroll 8
        for (int d = 0; d < 64; d++) s += bb[h * 64 + d] * Wh[d * 64 + e];
        if (side) g_biasK[col] = s + b_h[col];
        else      g_biasQ[col] = s;
    } else if (bx < 132) {
        int q = bx - 4;
        int side = q >> 6;
        q &= 63;
        int h = q >> 3, k0 = (q & 7) * 64;
        const float* W = side ? Wk : Wq;
        const float* Wh = (side ? Wk_h : Wq_h) + h * 4096;
        float* C = (side ? g_WkEffT : g_WqEffT) + h * 64 * 512;
#pragma unroll
        for (int r = 0; r < 4; r++) {
            int idx = tid + r * 256;
            int row = idx >> 4, c4 = (idx & 15) << 2;
            *(float4*)&sm[0][row][c4] = *(const float4*)&W[(long)(k0 + row) * 512 + h * 64 + c4];
            *(float4*)&sm[1][row][c4] = *(const float4*)&Wh[row * 64 + c4];
        }
        __syncthreads();
        const int tmm = (tid >> 4) * 4, tnn = (tid & 15) * 4;
        float acc[4][4] = {};
#pragma unroll 8
        for (int d = 0; d < 64; d++) {
            float a[4], b[4];
#pragma unroll
            for (int i = 0; i < 4; i++) a[i] = sm[0][tmm + i][d];
            *(float4*)b = *(const float4*)&sm[1][d][tnn];
#pragma unroll
            for (int i = 0; i < 4; i++)
#pragma unroll
                for (int j = 0; j < 4; j++) acc[i][j] += a[i] * b[j];
        }
#pragma unroll
        for (int i = 0; i < 4; i++)
#pragma unroll
            for (int j = 0; j < 4; j++)
                C[(long)(tnn + j) * 512 + k0 + tmm + i] = acc[i][j];
    } else {
        int q = bx - 132;
        int zz = q >> 8;
        q &= 255;
        int by = q >> 4, bxx = q & 15;
        const float* S = zz ? Wo : Wk;
        float* D = zz ? g_WoT : g_WkT;
        float (*t)[33] = (float(*)[33]) & sm[0][0][0];
        int lx = tid & 31, ly = tid >> 5;
        int x = bxx * 32 + lx, y0 = by * 32;
#pragma unroll
        for (int r = ly; r < 32; r += 8) t[r][lx] = S[(long)(y0 + r) * 512 + x];
        __syncthreads();
        int xo = y0 + lx;
#pragma unroll
        for (int r = ly; r < 32; r += 8) D[(long)(bxx * 32 + r) * 512 + xo] = t[lx][r];
    }
}

// ==================== tf32 mma.sync GEMM core (R14 proven form) ====================
// Double-buffered smem, K-chunk 32, dynamic chunk loop, 1-deep register stage.
// Tile MT x 64 (MT in {32,64}), 8 warps 2x4.
// C = A[Mx512] @ B^T (B K-major [512n][512k]) + bias.
// mode 0: row-major C. mode 1: [z][n&63][t] scatter. mode 2: [z][t][n&63].
template <int MT>
__device__ __forceinline__ void gemm_core(
    uint32_t* As, uint32_t* Bs,  // As: 2*ASTRIDE, Bs: 2*2048
    const float* __restrict__ A, const float* __restrict__ B,
    const float* __restrict__ bias, float* __restrict__ C,
    int m0, int n0, int mode) {
    constexpr int MI = MT / 32;          // mma m-tiles per warp
    constexpr int AR = MT / 32;          // A float4s per thread per chunk
    constexpr int ASTRIDE = (MT / 16) * 4 * 128;
    const int tid = threadIdx.x;
    const int wid = tid >> 5, lane = tid & 31;
    const int wm = wid >> 2, wn = wid & 3;

    float4 apf[AR], bpf[2];
    auto ldg = [&](int ch) {
        int k0 = ch << 5;
#pragma unroll
        for (int r = 0; r < AR; r++) {
            int j = tid + 256 * r;
            int row = j >> 3, c4 = (j & 7) << 2;
            apf[r] = *(const float4*)&A[(long)(m0 + row) * 512 + k0 + c4];
        }
#pragma unroll
        for (int r = 0; r < 2; r++) {
            int j = tid + 256 * r;
            int row = j >> 3, c4 = (j & 7) << 2;
            bpf[r] = *(const float4*)&B[(long)(n0 + row) * 512 + k0 + c4];
        }
    };
    auto sts = [&](int buf) {
#pragma unroll
        for (int r = 0; r < AR; r++) {
            int j = tid + 256 * r;
            int row = j >> 3, c4 = (j & 7) << 2;
            int ks = c4 >> 3, chi = (c4 >> 2) & 1;
            int mt = row >> 4, rlo = row & 15;
            int reg = (rlo >> 3) + (chi << 1);
            int off = buf * ASTRIDE + (mt * 4 + ks) * 128 + (rlo & 7) * 16 + reg;
            As[off + 0] = f2tf32(apf[r].x);
            As[off + 4] = f2tf32(apf[r].y);
            As[off + 8] = f2tf32(apf[r].z);
            As[off + 12] = f2tf32(apf[r].w);
        }
#pragma unroll
        for (int r = 0; r < 2; r++) {
            int j = tid + 256 * r;
            int row = j >> 3, c4 = (j & 7) << 2;
            int ks = c4 >> 3, chi = (c4 >> 2) & 1;
            int nt = row >> 3, g = row & 7;
            int off = buf * 2048 + (nt * 4 + ks) * 64 + g * 8 + chi;
            Bs[off + 0] = f2tf32(bpf[r].x);
            Bs[off + 2] = f2tf32(bpf[r].y);
            Bs[off + 4] = f2tf32(bpf[r].z);
            Bs[off + 6] = f2tf32(bpf[r].w);
        }
    };

    float acc[MI][2][4] = {};
    auto compute = [&](int buf) {
#pragma unroll
        for (int ks = 0; ks < 4; ks++) {
            uint32_t a[MI][4], b[2][2];
#pragma unroll
            for (int i = 0; i < MI; i++) {
                int mt = wm * MI + i;
                uint4 v = *(const uint4*)&As[buf * ASTRIDE + (mt * 4 + ks) * 128 + lane * 4];
                a[i][0] = v.x; a[i][1] = v.y; a[i][2] = v.z; a[i][3] = v.w;
            }
#pragma unroll
            for (int j = 0; j < 2; j++) {
                int nt = wn * 2 + j;
                uint2 v = *(const uint2*)&Bs[buf * 2048 + (nt * 4 + ks) * 64 + lane * 2];
                b[j][0] = v.x; b[j][1] = v.y;
            }
#pragma unroll
            for (int i = 0; i < MI; i++)
#pragma unroll
                for (int j = 0; j < 2; j++) mma_m16n8k8(acc[i][j], a[i], b[j]);
        }
    };

    ldg(0);
    sts(0);
    __syncthreads();
    for (int ch = 0; ch < 16; ch++) {
        if (ch + 1 < 16) ldg(ch + 1);
        compute(ch & 1);
        if (ch + 1 < 16) sts((ch + 1) & 1);
        __syncthreads();
    }

    const int g = lane >> 2, t4 = lane & 3;
#pragma unroll
    for (int i = 0; i < MI; i++)
#pragma unroll
        for (int j = 0; j < 2; j++) {
            int m = m0 + wm * (MI * 16) + i * 16 + g;
            int n = n0 + wn * 16 + j * 8 + t4 * 2;
            float c0 = acc[i][j][0], c1 = acc[i][j][1];
            float c2 = acc[i][j][2], c3 = acc[i][j][3];
            if (bias) {
                float b0 = bias[n], b1 = bias[n + 1];
                c0 += b0; c1 += b1; c2 += b0; c3 += b1;
            }
            if (mode == 0) {
                *(float2*)&C[(long)m * 512 + n] = make_float2(c0, c1);
                *(float2*)&C[(long)(m + 8) * 512 + n] = make_float2(c2, c3);
            } else if (mode == 1) {
                int bb = m >> 9, t = m & 511;
                long base0 = ((long)((bb << 3) + (n >> 6)) * 64 + (n & 63)) * 512;
                C[base0 + t] = c0;
                C[base0 + 512 + t] = c1;
                C[base0 + t + 8] = c2;
                C[base0 + 512 + t + 8] = c3;
            } else {
                int bb = m >> 9, t = m & 511;
                long r0 = ((long)((bb << 3) + (n >> 6)) * 512 + t) * 64 + (n & 63);
                *(float2*)&C[r0] = make_float2(c0, c1);
                *(float2*)&C[r0 + 8 * 64] = make_float2(c2, c3);
            }
        }
}

// three projections in one launch (z = task), 64x64 tiles (grid 384)
__global__ void __launch_bounds__(256) proj_mma(
    const float* __restrict__ query, const float* __restrict__ key,
    const float* __restrict__ bk) {
    __shared__ uint32_t As[2][2048], Bs[2][2048];  // 32 KB
    int task = blockIdx.z;
    int m0 = blockIdx.y * 64, n0 = blockIdx.x * 64;
    if (task == 0)
        gemm_core<64>(&As[0][0], &Bs[0][0], query, g_WqEffT, g_biasQ, g_qhE, m0, n0, 1);
    else if (task == 1)
        gemm_core<64>(&As[0][0], &Bs[0][0], key, g_WkEffT, g_biasK, g_khbE, m0, n0, 1);
    else
        gemm_core<64>(&As[0][0], &Bs[0][0], key, g_WkT, bk, g_KpR, m0, n0, 2);
}
// output projection, 32x64 tiles -> 256 CTAs
__global__ void __launch_bounds__(256) outg_mma(
    const float* __restrict__ bo, float* __restrict__ out) {
    __shared__ uint32_t As[2][1024], Bs[2][2048];  // 24 KB
    gemm_core<32>(&As[0][0], &Bs[0][0], g_merged, g_WoT, bo, out,
                  blockIdx.y * 32, blockIdx.x * 64, 0);
}

// ==================== fused score + exp + AV, s-split partials ====================
// grid (16 t-tiles, 16 z, 4 s-quarters). Per CTA: rows t0..t0+31 of one (b,h),
// s-chunks [2*sq, 2*sq+2). Scores are bounded (|score| ~< 1.5), so exp is taken
// WITHOUT max-subtraction; the LAST CTA of each (z,t-tile) group combines the
// 4 quarter-partials into g_merged (atomic counter, fence-ordered).
__global__ void __launch_bounds__(256) fused_attn(const float* __restrict__ va) {
    const int t0 = blockIdx.x * 32;
    const int z = blockIdx.y;
    const int sq = blockIdx.z;
    const int b = z >> 3, h = z & 7;
    __shared__ float qse[64][36];   // [e][t]
    __shared__ float kse[64][68];   // [e][s]; rows 0..31 reused as p[t][s]
    __shared__ float kp[64][68];    // [s][d]
    __shared__ float vsh[64];
    __shared__ int oldc;
    const int tid = threadIdx.x;
    const float* qbase = g_qhE + (long)z * 32768;
    const float* kbase = g_khbE + (long)z * 32768;
    const float* kpbase = g_KpR + (long)z * 32768;

#pragma unroll
    for (int r = 0; r < 2; r++) {
        int idx = tid + r * 256;
        int row = idx >> 3, c4 = (idx & 7) << 2;
        *(float4*)&qse[row][c4] = *(const float4*)&qbase[(long)row * 512 + t0 + c4];
    }
    if (tid < 64) vsh[tid] = va[h * 64 + tid];

    const int tm = (tid >> 4) * 2, tn = (tid & 15) * 4;
    float out[2][4] = {};
    float lrow[2] = {0.f, 0.f};
    float* pbuf = &kse[0][0];

    for (int c = sq * 2; c < sq * 2 + 2; c++) {
        const int s0 = c * 64;
        __syncthreads();  // prior chunk consumers done with kse/kp
#pragma unroll
        for (int r = 0; r < 4; r++) {
            int idx = tid + r * 256;
            int row = idx >> 4, c4 = (idx & 15) << 2;
            *(float4*)&kse[row][c4] = *(const float4*)&kbase[(long)row * 512 + s0 + c4];
            *(float4*)&kp[row][c4] = *(const float4*)&kpbase[(long)(s0 + row) * 64 + c4];
        }
        __syncthreads();

        float sc[2][4] = {};
#pragma unroll 8
        for (int e = 0; e < 64; e++) {
            float vv = vsh[e];
            float2 q2 = *(const float2*)&qse[e][tm];
            float4 kv = *(const float4*)&kse[e][tn];
            sc[0][0] += vv * tanh_fast(q2.x + kv.x);
            sc[0][1] += vv * tanh_fast(q2.x + kv.y);
            sc[0][2] += vv * tanh_fast(q2.x + kv.z);
            sc[0][3] += vv * tanh_fast(q2.x + kv.w);
            sc[1][0] += vv * tanh_fast(q2.y + kv.x);
            sc[1][1] += vv * tanh_fast(q2.y + kv.y);
            sc[1][2] += vv * tanh_fast(q2.y + kv.z);
            sc[1][3] += vv * tanh_fast(q2.y + kv.w);
        }

        // p = exp(score) directly (bounded scores; no max subtraction needed)
#pragma unroll
        for (int i = 0; i < 2; i++) {
#pragma unroll
            for (int j = 0; j < 4; j++) sc[i][j] = __expf(sc[i][j]);
            lrow[i] += (sc[i][0] + sc[i][1]) + (sc[i][2] + sc[i][3]);
        }

        __syncthreads();  // all kse reads finished (pbuf aliases kse)
        *(float4*)&pbuf[tm * 68 + tn] = make_float4(sc[0][0], sc[0][1], sc[0][2], sc[0][3]);
        *(float4*)&pbuf[(tm + 1) * 68 + tn] = make_float4(sc[1][0], sc[1][1], sc[1][2], sc[1][3]);
        __syncthreads();

#pragma unroll 4
        for (int s = 0; s < 64; s++) {
            float p0 = pbuf[tm * 68 + s];
            float p1 = pbuf[(tm + 1) * 68 + s];
            float4 kv = *(const float4*)&kp[s][tn];
            out[0][0] += p0 * kv.x; out[0][1] += p0 * kv.y;
            out[0][2] += p0 * kv.z; out[0][3] += p0 * kv.w;
            out[1][0] += p1 * kv.x; out[1][1] += p1 * kv.y;
            out[1][2] += p1 * kv.z; out[1][3] += p1 * kv.w;
        }
    }

    // reduce lrow across the 16 threads sharing each row pair, write partials
#pragma unroll
    for (int o = 8; o; o >>= 1) {
        lrow[0] += __shfl_xor_sync(0xffffffffu, lrow[0], o);
        lrow[1] += __shfl_xor_sync(0xffffffffu, lrow[1], o);
    }
    long pb0 = ((long)((z << 2) + sq) * 512 + t0 + tm) * 64 + tn;
    *(float4*)&g_part[pb0] = make_float4(out[0][0], out[0][1], out[0][2], out[0][3]);
    *(float4*)&g_part[pb0 + 64] = make_float4(out[1][0], out[1][1], out[1][2], out[1][3]);
    if ((tid & 15) == 0) {
        int lb = ((z << 2) + sq) * 512 + t0 + tm;
        g_lpart[lb] = lrow[0];
        g_lpart[lb + 1] = lrow[1];
    }

    // ---- last-CTA-wins combine into g_merged ----
    __threadfence();  // release: partials visible before counter bump
    __syncthreads();  // all threads' stores precede the fence/atomic thread's view
    if (tid == 0) oldc = atomicAdd(&g_cnt[z * 16 + blockIdx.x], 1);
    __syncthreads();
    if (oldc == 3) {
        __threadfence();  // acquire: see other CTAs' partials
#pragma unroll
        for (int r2 = 0; r2 < 2; r2++) {
            int fi = tid + r2 * 256;      // 0..511 float4 slots (32 rows x 16)
            int row = fi >> 4;
            int c4 = (fi & 15) << 2;
            int t = t0 + row;
            float4 s = make_float4(0.f, 0.f, 0.f, 0.f);
            float l = 0.f;
#pragma unroll
            for (int q = 0; q < 4; q++) {
                long base = (long)((z << 2) + q) * 512 + t;
                float4 v = *(const float4*)&g_part[(base << 6) + c4];
                s.x += v.x; s.y += v.y; s.z += v.z; s.w += v.w;
                l += g_lpart[base];
            }
            float inv = __fdividef(1.f, l);
            *(float4*)&g_merged[(long)(b * 512 + t) * 512 + h * 64 + c4] =
                make_float4(s.x * inv, s.y * inv, s.z * inv, s.w * inv);
        }
    }
}

// ---------------- launcher ----------------
extern "C" void kernel_launch(void* const* d_in, const int* in_sizes, int n_in,
                              void* d_out, int out_size) {
    const float* query = (const float*)d_in[0];
    const float* key   = (const float*)d_in[1];
    const float* Wq   = (const float*)d_in[3];
    const float* bq   = (const float*)d_in[4];
    const float* Wk   = (const float*)d_in[5];
    const float* bk   = (const float*)d_in[6];
    const float* Wq_h = (const float*)d_in[9];
    const float* Wk_h = (const float*)d_in[10];
    const float* va_h = (const float*)d_in[11];
    const float* b_h  = (const float*)d_in[12];
    const float* Wo   = (const float*)d_in[13];
    const float* bo   = (const float*)d_in[14];
    float* out = (float*)d_out;

    prep_all<<<644, 256>>>(bq, Wq_h, bk, Wk_h, b_h, Wq, Wk, Wo);
    proj_mma<<<dim3(8, 16, 3), 256>>>(query, key, bk);
    fused_attn<<<dim3(16, 16, 4), 256>>>(va_h);
    outg_mma<<<dim3(8, 32), 256>>>(bo, out);
}